// round 14
// baseline (speedup 1.0000x reference)
#include <cuda_runtime.h>
#include <cuda_bf16.h>
#include <cstdint>

#define D_IN 1024
#define DP   256
#define CC   256
#define BM   128
#define BK   64
#define NT   512

// padded SMEM row strides (bytes) -> conflict-free ldmatrix without XOR swizzle
#define SA 144    // A/B tiles: 64 bf16 = 128B + 16B pad   (144/4 = 36 ≡ 4 mod 32)
#define SB 144
#define SZ 528    // Z rows: 256 bf16 = 512B + 16B pad     (528/4 = 132 ≡ 4 mod 32)

// smem layout (byte offsets)
#define OFF_A0   0
#define OFF_A1   (OFF_A0 + BM * SA)         // 18432
#define OFF_B0   (OFF_A1 + BM * SA)         // 36864
#define OFF_B1   (OFF_B0 + 256 * SB)        // 73728
#define OFF_Z    (OFF_B1 + 256 * SB)        // 110592
#define OFF_MP   (OFF_Z + BM * SZ)          // 178176
#define OFF_P2   (OFF_MP + 1024)            // 179200
#define OFF_S2   (OFF_P2 + 1024)            // 180224 (row sumsq, 128 f32)
#define OFF_INV  (OFF_S2 + 512)             // 180736
#define OFF_Z2N  (OFF_INV + 512)            // 181248
#define SMEM_SZ  (OFF_Z2N + 512)            // 181760 bytes

__device__ float g_mproj[DP];                 // mean @ proj
__device__ float g_p2[CC];                    // ||p_c||^2
__device__ __nv_bfloat16 g_projT[DP * D_IN];  // [n][k] = proj[k][n], bf16
__device__ __nv_bfloat16 g_protosb[CC * DP];  // bf16 copy (already K-major)

// ---------------- helpers ----------------
__device__ __forceinline__ uint32_t smem_u32(const void* p) {
    uint32_t a;
    asm("{ .reg .u64 t; cvta.to.shared.u64 t, %1; cvt.u32.u64 %0, t; }" : "=r"(a) : "l"(p));
    return a;
}
__device__ __forceinline__ void ldsm4(uint32_t (&r)[4], uint32_t addr) {
    asm volatile("ldmatrix.sync.aligned.m8n8.x4.shared.b16 {%0,%1,%2,%3}, [%4];"
        : "=r"(r[0]), "=r"(r[1]), "=r"(r[2]), "=r"(r[3]) : "r"(addr));
}
__device__ __forceinline__ void mma16816(float (&d)[4], const uint32_t (&a)[4],
                                         uint32_t b0, uint32_t b1) {
    asm volatile("mma.sync.aligned.m16n8k16.row.col.f32.bf16.bf16.f32 "
        "{%0,%1,%2,%3},{%4,%5,%6,%7},{%8,%9},{%0,%1,%2,%3};"
        : "+f"(d[0]), "+f"(d[1]), "+f"(d[2]), "+f"(d[3])
        : "r"(a[0]), "r"(a[1]), "r"(a[2]), "r"(a[3]), "r"(b0), "r"(b1));
}
__device__ __forceinline__ void cp16(uint32_t dst, const void* src) {
    asm volatile("cp.async.cg.shared.global [%0], [%1], 16;" :: "r"(dst), "l"(src) : "memory");
}
#define CP_COMMIT() asm volatile("cp.async.commit_group;" ::: "memory")
#define CP_WAIT0()  asm volatile("cp.async.wait_group 0;" ::: "memory")

// ---------------- precompute kernels ----------------
__global__ void pre_convP(const float* __restrict__ proj) {   // [k][n] fp32 -> [n][k] bf16
    int i = blockIdx.x * 256 + threadIdx.x;
    int k = i >> 8, n = i & 255;
    g_projT[n * D_IN + k] = __float2bfloat16(proj[i]);
}
__global__ void pre_convC(const float* __restrict__ protos) {
    int i = blockIdx.x * 256 + threadIdx.x;
    g_protosb[i] = __float2bfloat16(protos[i]);
}
__global__ void pre_scalars(const float* __restrict__ mean,
                            const float* __restrict__ proj,
                            const float* __restrict__ protos) {
    int g = blockIdx.x * 4 + (threadIdx.x >> 5);
    int lane = threadIdx.x & 31;
    float a = 0.f;
    for (int k = lane; k < D_IN; k += 32) a = fmaf(mean[k], proj[k * DP + g], a);
#pragma unroll
    for (int o = 16; o; o >>= 1) a += __shfl_xor_sync(~0u, a, o);
    if (!lane) g_mproj[g] = a;
    float s = 0.f;
    const float* p = protos + (size_t)g * DP;
    for (int d = lane; d < DP; d += 32) s = fmaf(p[d], p[d], s);
#pragma unroll
    for (int o = 16; o; o >>= 1) s += __shfl_xor_sync(~0u, s, o);
    if (!lane) g_p2[g] = s;
}

// ---------------- fused main kernel ----------------
__global__ void __launch_bounds__(NT, 1)
proto_mma(const float* __restrict__ X, float* __restrict__ out, int N) {
    extern __shared__ __align__(16) char smem[];
    const uint32_t sbase = smem_u32(smem);
    const int tid = threadIdx.x;
    const int wid = tid >> 5, lane = tid & 31;
    const int wm = wid & 3;          // 4 warps over M (32 rows each)
    const int wn = wid >> 2;         // 4 warps over N (64 cols each)
    const int rowBase = blockIdx.x * BM;

    if (tid < 256) {
        ((float*)(smem + OFF_MP))[tid] = g_mproj[tid];
        ((float*)(smem + OFF_P2))[tid] = g_p2[tid];
    }
    if (tid < BM) ((float*)(smem + OFF_S2))[tid] = 0.f;
    __syncthreads();

    float acc[2][8][4];
#pragma unroll
    for (int i = 0; i < 2; ++i)
#pragma unroll
        for (int j = 0; j < 8; ++j)
#pragma unroll
            for (int c = 0; c < 4; ++c) acc[i][j][c] = 0.f;

    // ---- A tile: split issue / store (16 staging regs) ----
    float4 av[4];
    auto loadA_issue = [&](int kb) {
#pragma unroll
        for (int ii = 0; ii < 4; ++ii) {
            int idx = tid + NT * ii;        // 2048 float4
            int r = idx >> 4, q = idx & 15;
            int gr = rowBase + r; if (gr >= N) gr = N - 1;
            av[ii] = *(const float4*)(X + (size_t)gr * D_IN + kb * BK + q * 4);
        }
    };
    auto storeA = [&](char* dst) {
#pragma unroll
        for (int ii = 0; ii < 4; ++ii) {
            int idx = tid + NT * ii;
            int r = idx >> 4, q = idx & 15;
            __nv_bfloat162 p0 = __floats2bfloat162_rn(av[ii].x, av[ii].y);
            __nv_bfloat162 p1 = __floats2bfloat162_rn(av[ii].z, av[ii].w);
            uint2 w; w.x = *(uint32_t*)&p0; w.y = *(uint32_t*)&p1;
            *(uint2*)(dst + r * SA + q * 8) = w;
        }
    };
    // ---- B tile via cp.async (bf16 global -> smem, no regs) ----
    auto cpB = [&](const __nv_bfloat16* src, size_t strideB, int kb, uint32_t dstOff) {
#pragma unroll
        for (int ii = 0; ii < 4; ++ii) {
            int idx = tid + NT * ii;        // 2048 x 16B
            int n = idx >> 3, o = idx & 7;
            cp16(sbase + dstOff + (uint32_t)(n * SB + o * 16),
                 (const char*)src + (size_t)n * strideB + (size_t)kb * 128 + o * 16);
        }
    };

    // ---- warp-tile compute (32x64) over one 64-wide K chunk ----
    auto compute = [&](uint32_t aBase, uint32_t bBase, int strideA) {
        const int aRow = wm * 32 + (lane & 15);
        const int bRowBase = wn * 64 + (lane >> 4) * 8 + (lane & 7);
#pragma unroll
        for (int s = 0; s < 4; ++s) {       // 4 k-steps of 16
            const int aCol = s * 32 + (lane >> 4) * 16;            // bytes
            const int bCol = s * 32 + ((lane >> 3) & 1) * 16;      // bytes
            uint32_t af[2][4], bfr[4][4];
#pragma unroll
            for (int i = 0; i < 2; ++i)
                ldsm4(af[i], aBase + (uint32_t)((aRow + i * 16) * strideA + aCol));
#pragma unroll
            for (int jj = 0; jj < 4; ++jj)
                ldsm4(bfr[jj], bBase + (uint32_t)((bRowBase + jj * 16) * SB + bCol));
#pragma unroll
            for (int i = 0; i < 2; ++i)
#pragma unroll
                for (int jj = 0; jj < 4; ++jj) {
                    mma16816(acc[i][2 * jj],     af[i], bfr[jj][0], bfr[jj][1]);
                    mma16816(acc[i][2 * jj + 1], af[i], bfr[jj][2], bfr[jj][3]);
                }
        }
    };

    // ================= Phase 1: Z = Xbf16 @ projT^T =================
    loadA_issue(0);
    cpB(g_projT, D_IN * 2, 0, OFF_B0);
    CP_COMMIT();
    storeA(smem + OFF_A0);
    CP_WAIT0();
    __syncthreads();
    for (int kb = 0; kb < 16; ++kb) {
        uint32_t aCur = sbase + ((kb & 1) ? OFF_A1 : OFF_A0);
        uint32_t bCur = sbase + ((kb & 1) ? OFF_B1 : OFF_B0);
        if (kb < 15) {
            loadA_issue(kb + 1);                                   // LDGs in flight
            cpB(g_projT, D_IN * 2, kb + 1, (kb & 1) ? OFF_B0 : OFF_B1);
            CP_COMMIT();
        }
        compute(aCur, bCur, SA);                                   // hides the LDG latency
        if (kb < 15) {
            storeA(smem + ((kb & 1) ? OFF_A0 : OFF_A1));
            CP_WAIT0();
        }
        __syncthreads();
    }

    // prefetch protos chunk 0 into B0 (free after kb=15 which used B1), overlap epilogue
    cpB(g_protosb, DP * 2, 0, OFF_B0);
    CP_COMMIT();

    // ======== Epilogue 1: center, row sumsq, stash unnormalized z (bf16) ========
    {
        const float* mp = (const float*)(smem + OFF_MP);
        float* s2 = (float*)(smem + OFF_S2);
        char* Zb = smem + OFF_Z;
        const int r0 = wm * 32 + (lane >> 2);
        const int cq = (lane & 3) * 2;
#pragma unroll
        for (int i = 0; i < 2; ++i) {
#pragma unroll
            for (int h = 0; h < 2; ++h) {
                const int r = r0 + i * 16 + h * 8;
                float ss = 0.f;
#pragma unroll
                for (int j = 0; j < 8; ++j) {
                    const int col = wn * 64 + j * 8 + cq;
                    float z0 = acc[i][j][2 * h]     - mp[col];
                    float z1 = acc[i][j][2 * h + 1] - mp[col + 1];
                    ss = fmaf(z0, z0, fmaf(z1, z1, ss));
                    __nv_bfloat162 pz = __floats2bfloat162_rn(z0, z1);
                    *(uint32_t*)(Zb + r * SZ + col * 2) = *(uint32_t*)&pz;
                }
                ss += __shfl_xor_sync(~0u, ss, 1);
                ss += __shfl_xor_sync(~0u, ss, 2);
                if ((lane & 3) == 0) atomicAdd(&s2[r], ss);
            }
        }
    }
    __syncthreads();
    if (tid < BM) {
        float ss = ((float*)(smem + OFF_S2))[tid];
        float inv = 1.f / fmaxf(sqrtf(ss), 1e-12f);       // F.normalize eps
        ((float*)(smem + OFF_INV))[tid] = inv;
        ((float*)(smem + OFF_Z2N))[tid] = ss * inv * inv; // ||z_n||^2
    }
#pragma unroll
    for (int i = 0; i < 2; ++i)
#pragma unroll
        for (int j = 0; j < 8; ++j)
#pragma unroll
            for (int c = 0; c < 4; ++c) acc[i][j][c] = 0.f;
    CP_WAIT0();
    __syncthreads();

    // ================= Phase 2: S = Zbf16 @ protos^T =================
    for (int kb = 0; kb < 4; ++kb) {
        uint32_t bCur = sbase + ((kb & 1) ? OFF_B1 : OFF_B0);
        if (kb < 3) {
            cpB(g_protosb, DP * 2, kb + 1, (kb & 1) ? OFF_B0 : OFF_B1);
            CP_COMMIT();
        }
        compute(sbase + OFF_Z + kb * 128, bCur, SZ);   // A = Z, k-offset 64 cols = 128B
        if (kb < 3) CP_WAIT0();
        __syncthreads();
    }

    // ======== Final epilogue: score = -sqrt(max(z2n + p2 - 2*inv*S, 0)) ========
    {
        const float* p2 = (const float*)(smem + OFF_P2);
        const float* invA = (const float*)(smem + OFF_INV);
        const float* z2A = (const float*)(smem + OFF_Z2N);
        const int r0 = wm * 32 + (lane >> 2);
        const int cq = (lane & 3) * 2;
#pragma unroll
        for (int i = 0; i < 2; ++i) {
#pragma unroll
            for (int h = 0; h < 2; ++h) {
                const int r = r0 + i * 16 + h * 8;
                const int row = rowBase + r;
                if (row >= N) continue;
                const float m2 = -2.f * invA[r];
                const float z2n = z2A[r];
                float* orow = out + (size_t)row * CC;
#pragma unroll
                for (int j = 0; j < 8; ++j) {
                    const int col = wn * 64 + j * 8 + cq;
                    float d0 = fmaf(m2, acc[i][j][2 * h],     z2n + p2[col]);
                    float d1 = fmaf(m2, acc[i][j][2 * h + 1], z2n + p2[col + 1]);
                    float2 v;
                    v.x = -sqrtf(fmaxf(d0, 0.f));
                    v.y = -sqrtf(fmaxf(d1, 0.f));
                    *(float2*)(orow + col) = v;
                }
            }
        }
    }
}

extern "C" void kernel_launch(void* const* d_in, const int* in_sizes, int n_in,
                              void* d_out, int out_size) {
    const float* X      = (const float*)d_in[0];
    const float* mean   = (const float*)d_in[1];
    const float* proj   = (const float*)d_in[2];
    const float* protos = (const float*)d_in[3];
    float* out = (float*)d_out;

    const int Din = in_sizes[1];           // 1024
    const int N   = in_sizes[0] / Din;     // 32768

    static bool attr_set = false;
    if (!attr_set) {
        cudaFuncSetAttribute(proto_mma, cudaFuncAttributeMaxDynamicSharedMemorySize, SMEM_SZ);
        attr_set = true;
    }

    pre_convP<<<(D_IN * DP) / 256, 256>>>(proj);
    pre_convC<<<(CC * DP) / 256, 256>>>(protos);
    pre_scalars<<<64, 128>>>(mean, proj, protos);
    proto_mma<<<(N + BM - 1) / BM, NT, SMEM_SZ>>>(X, out, N);
}

// round 17
// speedup vs baseline: 1.3498x; 1.3498x over previous
#include <cuda_runtime.h>
#include <cuda_bf16.h>
#include <cstdint>

#define D_IN 1024
#define DP   256
#define CC   256
#define BM   128
#define BK   64
#define NT   256

// padded SMEM row strides (bytes) -> conflict-free ldmatrix without XOR swizzle
#define SA 144    // A/B tiles: 64 bf16 = 128B + 16B pad   (144/4 = 36 ≡ 4 mod 32)
#define SB 144
#define SZ 528    // Z rows: 256 bf16 = 512B + 16B pad     (528/4 = 132 ≡ 4 mod 32)

// smem layout (byte offsets)
#define OFF_A0   0
#define OFF_A1   (OFF_A0 + BM * SA)         // 18432
#define OFF_B0   (OFF_A1 + BM * SA)         // 36864
#define OFF_B1   (OFF_B0 + 256 * SB)        // 73728
#define OFF_Z    (OFF_B1 + 256 * SB)        // 110592
#define OFF_MP   (OFF_Z + BM * SZ)          // 178176
#define OFF_P2   (OFF_MP + 1024)            // 179200
#define OFF_S2   (OFF_P2 + 1024)            // 180224 (row sumsq, 128 f32)
#define OFF_INV  (OFF_S2 + 512)             // 180736
#define OFF_Z2N  (OFF_INV + 512)            // 181248
#define SMEM_SZ  (OFF_Z2N + 512)            // 181760 bytes

__device__ float g_mproj[DP];                 // mean @ proj
__device__ float g_p2[CC];                    // ||p_c||^2
__device__ __nv_bfloat16 g_projT[DP * D_IN];  // [n][k] = proj[k][n], bf16
__device__ __nv_bfloat16 g_protosb[CC * DP];  // bf16 copy (already K-major)

// ---------------- helpers ----------------
__device__ __forceinline__ uint32_t smem_u32(const void* p) {
    uint32_t a;
    asm("{ .reg .u64 t; cvta.to.shared.u64 t, %1; cvt.u32.u64 %0, t; }" : "=r"(a) : "l"(p));
    return a;
}
__device__ __forceinline__ void ldsm4(uint32_t (&r)[4], uint32_t addr) {
    asm volatile("ldmatrix.sync.aligned.m8n8.x4.shared.b16 {%0,%1,%2,%3}, [%4];"
        : "=r"(r[0]), "=r"(r[1]), "=r"(r[2]), "=r"(r[3]) : "r"(addr));
}
__device__ __forceinline__ void mma16816(float (&d)[4], const uint32_t (&a)[4],
                                         uint32_t b0, uint32_t b1) {
    asm volatile("mma.sync.aligned.m16n8k16.row.col.f32.bf16.bf16.f32 "
        "{%0,%1,%2,%3},{%4,%5,%6,%7},{%8,%9},{%0,%1,%2,%3};"
        : "+f"(d[0]), "+f"(d[1]), "+f"(d[2]), "+f"(d[3])
        : "r"(a[0]), "r"(a[1]), "r"(a[2]), "r"(a[3]), "r"(b0), "r"(b1));
}
__device__ __forceinline__ void cp16(uint32_t dst, const void* src) {
    asm volatile("cp.async.cg.shared.global [%0], [%1], 16;" :: "r"(dst), "l"(src) : "memory");
}
#define CP_COMMIT() asm volatile("cp.async.commit_group;" ::: "memory")
#define CP_WAIT0()  asm volatile("cp.async.wait_group 0;" ::: "memory")
__device__ __forceinline__ void stcs2(float* p, float x, float y) {
    asm volatile("st.global.cs.v2.f32 [%0], {%1,%2};" :: "l"(p), "f"(x), "f"(y) : "memory");
}

// ---------------- merged precompute kernel ----------------
// blocks [0,1024): projT convert; [1024,1280): protos convert; [1280,1312): scalars
__global__ void __launch_bounds__(256)
pre_all(const float* __restrict__ mean, const float* __restrict__ proj,
        const float* __restrict__ protos) {
    const int b = blockIdx.x, tid = threadIdx.x;
    if (b < 1024) {
        int i = b * 256 + tid;                 // [k][n] fp32 -> [n][k] bf16
        int k = i >> 8, n = i & 255;
        g_projT[n * D_IN + k] = __float2bfloat16(proj[i]);
    } else if (b < 1280) {
        int i = (b - 1024) * 256 + tid;
        g_protosb[i] = __float2bfloat16(protos[i]);
    } else {
        int g = (b - 1280) * 8 + (tid >> 5);   // 32 blocks x 8 warps = 256
        int lane = tid & 31;
        float a = 0.f;
        for (int k = lane; k < D_IN; k += 32) a = fmaf(mean[k], proj[k * DP + g], a);
#pragma unroll
        for (int o = 16; o; o >>= 1) a += __shfl_xor_sync(~0u, a, o);
        if (!lane) g_mproj[g] = a;
        float s = 0.f;
        const float* p = protos + (size_t)g * DP;
        for (int d = lane; d < DP; d += 32) s = fmaf(p[d], p[d], s);
#pragma unroll
        for (int o = 16; o; o >>= 1) s += __shfl_xor_sync(~0u, s, o);
        if (!lane) g_p2[g] = s;
    }
}

// ---------------- fused main kernel ----------------
__global__ void __launch_bounds__(NT, 1)
proto_mma(const float* __restrict__ X, float* __restrict__ out, int N) {
    extern __shared__ __align__(16) char smem[];
    const uint32_t sbase = smem_u32(smem);
    const int tid = threadIdx.x;
    const int wid = tid >> 5, lane = tid & 31;
    const int wm = wid & 1;          // 2 warps over M (64 rows each)
    const int wn = wid >> 1;         // 4 warps over N (64 cols each)
    const int rowBase = blockIdx.x * BM;

    if (tid < 256) {
        ((float*)(smem + OFF_MP))[tid] = g_mproj[tid];
        ((float*)(smem + OFF_P2))[tid] = g_p2[tid];
    }
    if (tid < BM) ((float*)(smem + OFF_S2))[tid] = 0.f;
    __syncthreads();

    float acc[4][8][4];
#pragma unroll
    for (int i = 0; i < 4; ++i)
#pragma unroll
        for (int j = 0; j < 8; ++j)
#pragma unroll
            for (int c = 0; c < 4; ++c) acc[i][j][c] = 0.f;

    // ---- A tile: HALF staging (16 regs). half=0 -> rows 0-63, half=1 -> rows 64-127 ----
    float4 av[4];
    auto loadA_half = [&](int kb, int half) {
#pragma unroll
        for (int m = 0; m < 4; ++m) {
            int idx = tid + NT * (half * 4 + m);    // 1024 float4 per half
            int r = idx >> 4, q = idx & 15;
            int gr = rowBase + r; if (gr >= N) gr = N - 1;
            av[m] = *(const float4*)(X + (size_t)gr * D_IN + kb * BK + q * 4);
        }
    };
    auto storeA_half = [&](char* dst, int half) {
#pragma unroll
        for (int m = 0; m < 4; ++m) {
            int idx = tid + NT * (half * 4 + m);
            int r = idx >> 4, q = idx & 15;
            __nv_bfloat162 p0 = __floats2bfloat162_rn(av[m].x, av[m].y);
            __nv_bfloat162 p1 = __floats2bfloat162_rn(av[m].z, av[m].w);
            uint2 w; w.x = *(uint32_t*)&p0; w.y = *(uint32_t*)&p1;
            *(uint2*)(dst + r * SA + q * 8) = w;
        }
    };
    // ---- B tile via cp.async (bf16 global -> smem, no regs) ----
    auto cpB = [&](const __nv_bfloat16* src, size_t strideB, int kb, uint32_t dstOff) {
#pragma unroll
        for (int ii = 0; ii < 8; ++ii) {
            int idx = tid + NT * ii;                // 2048 x 16B
            int n = idx >> 3, o = idx & 7;
            cp16(sbase + dstOff + (uint32_t)(n * SB + o * 16),
                 (const char*)src + (size_t)n * strideB + (size_t)kb * 128 + o * 16);
        }
    };

    // ---- one 16-wide k-step of the 64x64 warp tile ----
    auto compute_s = [&](uint32_t aBase, uint32_t bBase, int strideA, int s) {
        const int aRow = wm * 64 + (lane & 15);
        const int bRowBase = wn * 64 + (lane >> 4) * 8 + (lane & 7);
        const int aCol = s * 32 + (lane >> 4) * 16;            // bytes
        const int bCol = s * 32 + ((lane >> 3) & 1) * 16;      // bytes
        uint32_t af[4][4], bfr[4][4];
#pragma unroll
        for (int i = 0; i < 4; ++i)
            ldsm4(af[i], aBase + (uint32_t)((aRow + i * 16) * strideA + aCol));
#pragma unroll
        for (int jj = 0; jj < 4; ++jj)
            ldsm4(bfr[jj], bBase + (uint32_t)((bRowBase + jj * 16) * SB + bCol));
#pragma unroll
        for (int i = 0; i < 4; ++i)
#pragma unroll
            for (int jj = 0; jj < 4; ++jj) {
                mma16816(acc[i][2 * jj],     af[i], bfr[jj][0], bfr[jj][1]);
                mma16816(acc[i][2 * jj + 1], af[i], bfr[jj][2], bfr[jj][3]);
            }
    };

    // ================= Phase 1: Z = Xbf16 @ projT^T =================
    loadA_half(0, 0); storeA_half(smem + OFF_A0, 0);
    loadA_half(0, 1); storeA_half(smem + OFF_A0, 1);
    cpB(g_projT, D_IN * 2, 0, OFF_B0);
    CP_COMMIT();
    CP_WAIT0();
    __syncthreads();
    for (int kb = 0; kb < 16; ++kb) {
        uint32_t aCur = sbase + ((kb & 1) ? OFF_A1 : OFF_A0);
        uint32_t bCur = sbase + ((kb & 1) ? OFF_B1 : OFF_B0);
        char* aNext = smem + ((kb & 1) ? OFF_A0 : OFF_A1);
        if (kb < 15) {
            loadA_half(kb + 1, 0);                              // 4 LDG in flight
            cpB(g_projT, D_IN * 2, kb + 1, (kb & 1) ? OFF_B0 : OFF_B1);
            CP_COMMIT();
        }
        compute_s(aCur, bCur, SA, 0);
        compute_s(aCur, bCur, SA, 1);
        if (kb < 15) {
            storeA_half(aNext, 0);
            loadA_half(kb + 1, 1);                              // hidden by s=2,3
        }
        compute_s(aCur, bCur, SA, 2);
        compute_s(aCur, bCur, SA, 3);
        if (kb < 15) {
            storeA_half(aNext, 1);
            CP_WAIT0();
        }
        __syncthreads();
    }

    // prefetch protos chunk 0 into B0 (free after kb=15 which used B1), overlap epilogue
    cpB(g_protosb, DP * 2, 0, OFF_B0);
    CP_COMMIT();

    // ======== Epilogue 1: center, row sumsq, stash unnormalized z (bf16) ========
    {
        const float* mp = (const float*)(smem + OFF_MP);
        float* s2 = (float*)(smem + OFF_S2);
        char* Zb = smem + OFF_Z;
        const int r0 = wm * 64 + (lane >> 2);
        const int cq = (lane & 3) * 2;
#pragma unroll
        for (int i = 0; i < 4; ++i) {
#pragma unroll
            for (int h = 0; h < 2; ++h) {
                const int r = r0 + i * 16 + h * 8;
                float ss = 0.f;
#pragma unroll
                for (int j = 0; j < 8; ++j) {
                    const int col = wn * 64 + j * 8 + cq;
                    float z0 = acc[i][j][2 * h]     - mp[col];
                    float z1 = acc[i][j][2 * h + 1] - mp[col + 1];
                    ss = fmaf(z0, z0, fmaf(z1, z1, ss));
                    __nv_bfloat162 pz = __floats2bfloat162_rn(z0, z1);
                    *(uint32_t*)(Zb + r * SZ + col * 2) = *(uint32_t*)&pz;
                }
                ss += __shfl_xor_sync(~0u, ss, 1);
                ss += __shfl_xor_sync(~0u, ss, 2);
                if ((lane & 3) == 0) atomicAdd(&s2[r], ss);
            }
        }
    }
    __syncthreads();
    if (tid < BM) {
        float ss = ((float*)(smem + OFF_S2))[tid];
        float inv = 1.f / fmaxf(sqrtf(ss), 1e-12f);       // F.normalize eps
        ((float*)(smem + OFF_INV))[tid] = inv;
        ((float*)(smem + OFF_Z2N))[tid] = ss * inv * inv; // ||z_n||^2
    }
#pragma unroll
    for (int i = 0; i < 4; ++i)
#pragma unroll
        for (int j = 0; j < 8; ++j)
#pragma unroll
            for (int c = 0; c < 4; ++c) acc[i][j][c] = 0.f;
    CP_WAIT0();
    __syncthreads();

    // ================= Phase 2: S = Zbf16 @ protos^T =================
    for (int kb = 0; kb < 4; ++kb) {
        uint32_t bCur = sbase + ((kb & 1) ? OFF_B1 : OFF_B0);
        if (kb < 3) {
            cpB(g_protosb, DP * 2, kb + 1, (kb & 1) ? OFF_B0 : OFF_B1);
            CP_COMMIT();
        }
        uint32_t aCur = sbase + OFF_Z + kb * 128;   // A = Z, k-offset 64 cols = 128B
        compute_s(aCur, bCur, SZ, 0);
        compute_s(aCur, bCur, SZ, 1);
        compute_s(aCur, bCur, SZ, 2);
        compute_s(aCur, bCur, SZ, 3);
        if (kb < 3) CP_WAIT0();
        __syncthreads();
    }

    // ======== Final epilogue: score = -sqrt(max(z2n + p2 - 2*inv*S, 0)) ========
    {
        const float* p2 = (const float*)(smem + OFF_P2);
        const float* invA = (const float*)(smem + OFF_INV);
        const float* z2A = (const float*)(smem + OFF_Z2N);
        const int r0 = wm * 64 + (lane >> 2);
        const int cq = (lane & 3) * 2;
#pragma unroll
        for (int i = 0; i < 4; ++i) {
#pragma unroll
            for (int h = 0; h < 2; ++h) {
                const int r = r0 + i * 16 + h * 8;
                const int row = rowBase + r;
                if (row >= N) continue;
                const float m2 = -2.f * invA[r];
                const float z2n = z2A[r];
                float* orow = out + (size_t)row * CC;
#pragma unroll
                for (int j = 0; j < 8; ++j) {
                    const int col = wn * 64 + j * 8 + cq;
                    float d0 = fmaf(m2, acc[i][j][2 * h],     z2n + p2[col]);
                    float d1 = fmaf(m2, acc[i][j][2 * h + 1], z2n + p2[col + 1]);
                    stcs2(orow + col, -sqrtf(fmaxf(d0, 0.f)), -sqrtf(fmaxf(d1, 0.f)));
                }
            }
        }
    }
}

extern "C" void kernel_launch(void* const* d_in, const int* in_sizes, int n_in,
                              void* d_out, int out_size) {
    const float* X      = (const float*)d_in[0];
    const float* mean   = (const float*)d_in[1];
    const float* proj   = (const float*)d_in[2];
    const float* protos = (const float*)d_in[3];
    float* out = (float*)d_out;

    const int Din = in_sizes[1];           // 1024
    const int N   = in_sizes[0] / Din;     // 32768

    static bool attr_set = false;
    if (!attr_set) {
        cudaFuncSetAttribute(proto_mma, cudaFuncAttributeMaxDynamicSharedMemorySize, SMEM_SZ);
        attr_set = true;
    }

    pre_all<<<1312, 256>>>(mean, proj, protos);
    proto_mma<<<(N + BM - 1) / BM, NT, SMEM_SZ>>>(X, out, N);
}